// round 1
// baseline (speedup 1.0000x reference)
#include <cuda_runtime.h>
#include <math.h>

#define Bb 2
#define Nn 2048
#define Dd 768
#define Ee 8
#define Hh 3072
#define Tt (Bb*Nn)        // 4096
#define KKEEP 819         // int(2048*0.4)
#define V_MAX 3.0f
#define FEAT_CLAMP 10.0f

// ---------------- scratch (device globals; no allocation allowed) ----------
__device__ int   g_cnt[Ee];
__device__ int   g_off[Ee];
__device__ int   g_list[Ee * Tt];
__device__ int   g_gtok[Tt];       // gathered row -> token
__device__ float g_ggate[Tt];      // gathered row -> gate weight
__device__ float g_gate[Tt];       // token -> gate weight
__device__ float g_score[Tt];      // token -> sigmoid score
__device__ float g_xg[Tt * Dd];    // gathered x rows (grouped by expert)
__device__ float g_y1[(size_t)Tt * Hh]; // gelu(x@W1+b1), gathered order
__device__ float g_ffn[Tt * Dd];   // ffn_out, token order
__device__ float g_v[Tt];
__device__ float g_thr[Bb];
__device__ float g_fr[Tt], g_fi[Tt]; // forward cf
__device__ float g_br[Tt], g_bi[Tt]; // backward cf

// ---------------- kernels --------------------------------------------------
__global__ void k_zero() {
    if (threadIdx.x < Ee) g_cnt[threadIdx.x] = 0;
}

// gating: logits->softmax top1, sigmoid score, bucket token by expert
__global__ void k_gate(const float* __restrict__ x, const float* __restrict__ Wg,
                       const float* __restrict__ bg, const float* __restrict__ Wm,
                       const float* __restrict__ bm) {
    int t = blockIdx.x;
    __shared__ float xs[Dd];
    __shared__ float red[256];
    __shared__ float logits[Ee];
    int tid = threadIdx.x;
    for (int d = tid; d < Dd; d += 256) xs[d] = x[t * Dd + d];
    __syncthreads();

    int w = tid >> 5, lane = tid & 31;
    float s = 0.f;
    for (int d = lane; d < Dd; d += 32) s += xs[d] * Wg[d * Ee + w];
    #pragma unroll
    for (int o = 16; o; o >>= 1) s += __shfl_xor_sync(0xffffffffu, s, o);
    if (lane == 0) logits[w] = s + bg[w];

    float sm = 0.f;
    for (int d = tid; d < Dd; d += 256) sm += xs[d] * Wm[d];
    red[tid] = sm;
    __syncthreads();
    for (int st = 128; st; st >>= 1) {
        if (tid < st) red[tid] += red[tid + st];
        __syncthreads();
    }
    if (tid == 0) {
        g_score[t] = 1.f / (1.f + expf(-(red[0] + bm[0])));
        float mx = logits[0]; int am = 0;
        #pragma unroll
        for (int e = 1; e < Ee; e++) if (logits[e] > mx) { mx = logits[e]; am = e; }
        float ssum = 0.f;
        #pragma unroll
        for (int e = 0; e < Ee; e++) ssum += expf(logits[e] - mx);
        g_gate[t] = 1.f / ssum;  // top-1 softmax prob
        int pos = atomicAdd(&g_cnt[am], 1);
        g_list[am * Tt + pos] = t;
    }
}

__global__ void k_off() {
    int acc = 0;
    for (int e = 0; e < Ee; e++) { g_off[e] = acc; acc += g_cnt[e]; }
}

// gather x rows into expert-grouped contiguous buffer
__global__ void k_gather(const float* __restrict__ x) {
    int g = blockIdx.x;   // gathered row in [0, Tt)
    int e = 0;
    #pragma unroll
    for (int q = 1; q < Ee; q++) if (g >= g_off[q]) e = q;
    int token = g_list[e * Tt + (g - g_off[e])];
    if (threadIdx.x == 0) { g_gtok[g] = token; g_ggate[g] = g_gate[token]; }
    const float4* src = (const float4*)(x + (size_t)token * Dd);
    float4* dst = (float4*)(g_xg + (size_t)g * Dd);
    dst[threadIdx.x] = src[threadIdx.x];   // 192 threads * float4 = 768
}

__device__ __forceinline__ float gelu_tanh(float u) {
    return 0.5f * u * (1.f + tanhf(0.7978845608028654f * (u + 0.044715f * u * u * u)));
}

// GEMM1: Y1 = gelu(Xg @ W1[e] + b1[e]); 128x128x8 tile, 8x8 micro
__global__ __launch_bounds__(256) void k_ffn1(const float* __restrict__ W1,
                                              const float* __restrict__ b1) {
    int e = blockIdx.x >> 5;
    int m0 = (blockIdx.x & 31) * 128;
    int cnt = g_cnt[e];
    if (m0 >= cnt) return;
    int goff = g_off[e];
    const float* A = g_xg + (size_t)goff * Dd;
    const float* Bp = W1 + (size_t)e * Dd * Hh;
    int n0 = blockIdx.y * 128;

    __shared__ float As[8][128];
    __shared__ float Bs[8][128];
    float acc[8][8];
    #pragma unroll
    for (int i = 0; i < 8; i++)
        #pragma unroll
        for (int j = 0; j < 8; j++) acc[i][j] = 0.f;

    int tid = threadIdx.x, tx = tid & 15, ty = tid >> 4;
    for (int k0 = 0; k0 < Dd; k0 += 8) {
        __syncthreads();
        #pragma unroll
        for (int i = tid; i < 1024; i += 256) {
            int m = i >> 3, k = i & 7;
            As[k][m] = (m0 + m < cnt) ? A[(size_t)(m0 + m) * Dd + k0 + k] : 0.f;
        }
        #pragma unroll
        for (int i = tid; i < 1024; i += 256) {
            int k = i >> 7, n = i & 127;
            Bs[k][n] = Bp[(size_t)(k0 + k) * Hh + n0 + n];
        }
        __syncthreads();
        #pragma unroll
        for (int k = 0; k < 8; k++) {
            float a[8], b[8];
            *(float4*)(a)     = *(const float4*)&As[k][ty * 4];
            *(float4*)(a + 4) = *(const float4*)&As[k][64 + ty * 4];
            *(float4*)(b)     = *(const float4*)&Bs[k][tx * 4];
            *(float4*)(b + 4) = *(const float4*)&Bs[k][64 + tx * 4];
            #pragma unroll
            for (int i = 0; i < 8; i++)
                #pragma unroll
                for (int j = 0; j < 8; j++) acc[i][j] += a[i] * b[j];
        }
    }
    #pragma unroll
    for (int i = 0; i < 8; i++) {
        int m = (i < 4) ? (ty * 4 + i) : (64 + ty * 4 + (i - 4));
        if (m0 + m >= cnt) continue;
        float* orow = g_y1 + (size_t)(goff + m0 + m) * Hh + n0;
        #pragma unroll
        for (int j = 0; j < 8; j++) {
            int n = (j < 4) ? (tx * 4 + j) : (64 + tx * 4 + (j - 4));
            float c = acc[i][j] + b1[e * Hh + n0 + n];
            orow[n] = gelu_tanh(c);
        }
    }
}

// GEMM2: ffn = gate * (Y1 @ W2[e] + b2[e]), scattered to token order
__global__ __launch_bounds__(256) void k_ffn2(const float* __restrict__ W2,
                                              const float* __restrict__ b2) {
    int e = blockIdx.x >> 5;
    int m0 = (blockIdx.x & 31) * 128;
    int cnt = g_cnt[e];
    if (m0 >= cnt) return;
    int goff = g_off[e];
    const float* A = g_y1 + (size_t)goff * Hh;
    const float* Bp = W2 + (size_t)e * Hh * Dd;
    int n0 = blockIdx.y * 128;

    __shared__ float As[8][128];
    __shared__ float Bs[8][128];
    float acc[8][8];
    #pragma unroll
    for (int i = 0; i < 8; i++)
        #pragma unroll
        for (int j = 0; j < 8; j++) acc[i][j] = 0.f;

    int tid = threadIdx.x, tx = tid & 15, ty = tid >> 4;
    for (int k0 = 0; k0 < Hh; k0 += 8) {
        __syncthreads();
        #pragma unroll
        for (int i = tid; i < 1024; i += 256) {
            int m = i >> 3, k = i & 7;
            As[k][m] = (m0 + m < cnt) ? A[(size_t)(m0 + m) * Hh + k0 + k] : 0.f;
        }
        #pragma unroll
        for (int i = tid; i < 1024; i += 256) {
            int k = i >> 7, n = i & 127;
            Bs[k][n] = Bp[(size_t)(k0 + k) * Dd + n0 + n];
        }
        __syncthreads();
        #pragma unroll
        for (int k = 0; k < 8; k++) {
            float a[8], b[8];
            *(float4*)(a)     = *(const float4*)&As[k][ty * 4];
            *(float4*)(a + 4) = *(const float4*)&As[k][64 + ty * 4];
            *(float4*)(b)     = *(const float4*)&Bs[k][tx * 4];
            *(float4*)(b + 4) = *(const float4*)&Bs[k][64 + tx * 4];
            #pragma unroll
            for (int i = 0; i < 8; i++)
                #pragma unroll
                for (int j = 0; j < 8; j++) acc[i][j] += a[i] * b[j];
        }
    }
    #pragma unroll
    for (int i = 0; i < 8; i++) {
        int m = (i < 4) ? (ty * 4 + i) : (64 + ty * 4 + (i - 4));
        if (m0 + m >= cnt) continue;
        int token = g_gtok[goff + m0 + m];
        float gate = g_ggate[goff + m0 + m];
        float* orow = g_ffn + (size_t)token * Dd + n0;
        #pragma unroll
        for (int j = 0; j < 8; j++) {
            int n = (j < 4) ? (tx * 4 + j) : (64 + tx * 4 + (j - 4));
            orow[n] = gate * (acc[i][j] + b2[e * Dd + n0 + n]);
        }
    }
}

// v = clip(ffn @ Wv + bv, -3, 3)
__global__ void k_v(const float* __restrict__ Wv, const float* __restrict__ bv) {
    int t = blockIdx.x;
    __shared__ float red[256];
    int tid = threadIdx.x;
    float s = 0.f;
    for (int d = tid; d < Dd; d += 256) s += g_ffn[t * Dd + d] * Wv[d];
    red[tid] = s;
    __syncthreads();
    for (int st = 128; st; st >>= 1) {
        if (tid < st) red[tid] += red[tid + st];
        __syncthreads();
    }
    if (tid == 0) {
        float v = red[0] + bv[0];
        g_v[t] = fminf(fmaxf(v, -V_MAX), V_MAX);
    }
}

// exact kth-largest per sequence via bitonic sort (ascending), thr = s[N-K]
__global__ void k_thr() {
    __shared__ float s[Nn];
    int b = blockIdx.x, tid = threadIdx.x;
    for (int i = tid; i < Nn; i += 1024) s[i] = g_score[b * Nn + i];
    for (int k = 2; k <= Nn; k <<= 1) {
        for (int j = k >> 1; j > 0; j >>= 1) {
            __syncthreads();
            for (int i = tid; i < Nn; i += 1024) {
                int ixj = i ^ j;
                if (ixj > i) {
                    bool up = ((i & k) == 0);
                    float a = s[i], c = s[ixj];
                    if ((a > c) == up) { s[i] = c; s[ixj] = a; }
                }
            }
        }
    }
    __syncthreads();
    if (tid == 0) g_thr[b] = s[Nn - KKEEP];
}

// sequential continued fractions (fwd + bwd, per batch)
__global__ void k_bk() {
    int id = threadIdx.x;
    if (id >= 2 * Bb) return;
    int b = id >> 1, dir = id & 1;
    float ar = 1e18f, ai = 0.f;
    if (dir == 0) {
        for (int i = 0; i < Nn; i++) {
            float dr = g_v[b * Nn + i];
            float den = ar * ar + ai * ai;
            float inv = 1.f / den;
            float nr = dr - ar * inv;
            float ni = -1.f + ai * inv;   // di = -ETA = -1
            ar = nr; ai = ni;
            g_fr[b * Nn + i] = ar; g_fi[b * Nn + i] = ai;
        }
    } else {
        for (int i = Nn - 1; i >= 0; i--) {
            float dr = g_v[b * Nn + i];
            float den = ar * ar + ai * ai;
            float inv = 1.f / den;
            float nr = dr - ar * inv;
            float ni = -1.f + ai * inv;
            ar = nr; ai = ni;
            g_br[b * Nn + i] = ar; g_bi[b * Nn + i] = ai;
        }
    }
}

// out = ffn + bk_scale * (feats @ Wo + bo)
__global__ void k_out(const float* __restrict__ Wo, const float* __restrict__ bo,
                      const float* __restrict__ bk, float* __restrict__ out) {
    int t = blockIdx.x;
    int b = t >> 11;   // t / Nn
    __shared__ float sfr, sfi, sbk;
    if (threadIdx.x == 0) {
        float v  = g_v[t];
        float cr = g_fr[t] + g_br[t] - v;
        float ci = g_fi[t] + g_bi[t] + 1.f;   // - di, di = -1
        float den = cr * cr + ci * ci;
        float gr =  cr / den;
        float gi = -ci / den;
        float m = (g_score[t] >= g_thr[b]) ? 1.f : 0.f;
        sfr = fminf(fmaxf(gr * m, -FEAT_CLAMP), FEAT_CLAMP);
        sfi = fminf(fmaxf(gi * m, -FEAT_CLAMP), FEAT_CLAMP);
        sbk = bk[0];
    }
    __syncthreads();
    float fr = sfr, fi = sfi, s = sbk;
    for (int d = threadIdx.x; d < Dd; d += 192)
        out[(size_t)t * Dd + d] = g_ffn[t * Dd + d] + s * (fr * Wo[d] + fi * Wo[Dd + d] + bo[d]);
}

// ---------------- launch ---------------------------------------------------
extern "C" void kernel_launch(void* const* d_in, const int* in_sizes, int n_in,
                              void* d_out, int out_size) {
    const float* x   = (const float*)d_in[0];
    const float* Wg  = (const float*)d_in[1];
    const float* bg  = (const float*)d_in[2];
    const float* W1  = (const float*)d_in[3];
    const float* b1  = (const float*)d_in[4];
    const float* W2  = (const float*)d_in[5];
    const float* b2  = (const float*)d_in[6];
    const float* Wv  = (const float*)d_in[7];
    const float* bv  = (const float*)d_in[8];
    const float* Wm  = (const float*)d_in[9];
    const float* bm  = (const float*)d_in[10];
    const float* Wo  = (const float*)d_in[11];
    const float* bo  = (const float*)d_in[12];
    const float* bks = (const float*)d_in[13];
    float* out = (float*)d_out;

    k_zero<<<1, 32>>>();
    k_gate<<<Tt, 256>>>(x, Wg, bg, Wm, bm);
    k_off<<<1, 1>>>();
    k_gather<<<Tt, 192>>>(x);
    k_ffn1<<<dim3(Ee * 32, Hh / 128), 256>>>(W1, b1);
    k_ffn2<<<dim3(Ee * 32, Dd / 128), 256>>>(W2, b2);
    k_v<<<Tt, 256>>>(Wv, bv);
    k_thr<<<Bb, 1024>>>();
    k_bk<<<1, 32>>>();
    k_out<<<Tt, 192>>>(Wo, bo, bks, out);
}

// round 4
// speedup vs baseline: 2.4271x; 2.4271x over previous
#include <cuda_runtime.h>
#include <math.h>
#include <stdint.h>

#define Bb 2
#define Nn 2048
#define Dd 768
#define Ee 8
#define Hh 3072
#define Tt (Bb*Nn)        // 4096
#define KKEEP 819         // int(2048*0.4)
#define V_MAX 3.0f
#define FEAT_CLAMP 10.0f

// ---------------- scratch (device globals; no allocation allowed) ----------
__device__ int   g_cnt[Ee];
__device__ int   g_off[Ee];
__device__ int   g_list[Ee * Tt];
__device__ int   g_gtok[Tt];
__device__ float g_ggate[Tt];
__device__ float g_gate[Tt];
__device__ float g_score[Tt];
__device__ float g_xg[Tt * Dd];
__device__ float g_y1[(size_t)Tt * Hh];
__device__ float g_ffn[Tt * Dd];
__device__ float g_v[Tt];
__device__ float g_thr[Bb];
__device__ float g_fr[Tt], g_fi[Tt];
__device__ float g_br[Tt], g_bi[Tt];

// ---------------- small helpers -------------------------------------------
__device__ __forceinline__ uint32_t f2tf32(float f) {
    uint32_t u; asm("cvt.rna.tf32.f32 %0, %1;" : "=r"(u) : "f"(f)); return u;
}
__device__ __forceinline__ void cp_async16(uint32_t dst, const void* src, int szbytes) {
    asm volatile("cp.async.cg.shared.global [%0], [%1], 16, %2;\n"
                 :: "r"(dst), "l"(src), "r"(szbytes));
}
__device__ __forceinline__ void cp_commit() { asm volatile("cp.async.commit_group;"); }
template<int N> __device__ __forceinline__ void cp_wait() {
    asm volatile("cp.async.wait_group %0;" :: "n"(N));
}
__device__ __forceinline__ void mma_tf32(float* d, const uint32_t* a, const uint32_t* b) {
    asm volatile(
        "mma.sync.aligned.m16n8k8.row.col.f32.tf32.tf32.f32 "
        "{%0,%1,%2,%3}, {%4,%5,%6,%7}, {%8,%9}, {%0,%1,%2,%3};\n"
        : "+f"(d[0]), "+f"(d[1]), "+f"(d[2]), "+f"(d[3])
        : "r"(a[0]), "r"(a[1]), "r"(a[2]), "r"(a[3]), "r"(b[0]), "r"(b[1]));
}
__device__ __forceinline__ float gelu_tanh(float u) {
    return 0.5f * u * (1.f + tanhf(0.7978845608028654f * (u + 0.044715f * u * u * u)));
}

// ---------------- kernels --------------------------------------------------
__global__ void k_zero() {
    if (threadIdx.x < Ee) g_cnt[threadIdx.x] = 0;
}

__global__ void k_gate(const float* __restrict__ x, const float* __restrict__ Wg,
                       const float* __restrict__ bg, const float* __restrict__ Wm,
                       const float* __restrict__ bm) {
    int t = blockIdx.x;
    __shared__ float xs[Dd];
    __shared__ float red[256];
    __shared__ float logits[Ee];
    int tid = threadIdx.x;
    for (int d = tid; d < Dd; d += 256) xs[d] = x[t * Dd + d];
    __syncthreads();

    int w = tid >> 5, lane = tid & 31;
    float s = 0.f;
    for (int d = lane; d < Dd; d += 32) s += xs[d] * Wg[d * Ee + w];
    #pragma unroll
    for (int o = 16; o; o >>= 1) s += __shfl_xor_sync(0xffffffffu, s, o);
    if (lane == 0) logits[w] = s + bg[w];

    float sm = 0.f;
    for (int d = tid; d < Dd; d += 256) sm += xs[d] * Wm[d];
    red[tid] = sm;
    __syncthreads();
    for (int st = 128; st; st >>= 1) {
        if (tid < st) red[tid] += red[tid + st];
        __syncthreads();
    }
    if (tid == 0) {
        g_score[t] = 1.f / (1.f + expf(-(red[0] + bm[0])));
        float mx = logits[0]; int am = 0;
        #pragma unroll
        for (int e = 1; e < Ee; e++) if (logits[e] > mx) { mx = logits[e]; am = e; }
        float ssum = 0.f;
        #pragma unroll
        for (int e = 0; e < Ee; e++) ssum += expf(logits[e] - mx);
        g_gate[t] = 1.f / ssum;
        int pos = atomicAdd(&g_cnt[am], 1);
        g_list[am * Tt + pos] = t;
    }
}

__global__ void k_off() {
    int acc = 0;
    for (int e = 0; e < Ee; e++) { g_off[e] = acc; acc += g_cnt[e]; }
}

__global__ void k_gather(const float* __restrict__ x) {
    int g = blockIdx.x;
    int e = 0;
    #pragma unroll
    for (int q = 1; q < Ee; q++) if (g >= g_off[q]) e = q;
    int token = g_list[e * Tt + (g - g_off[e])];
    if (threadIdx.x == 0) { g_gtok[g] = token; g_ggate[g] = g_gate[token]; }
    const float4* src = (const float4*)(x + (size_t)token * Dd);
    float4* dst = (float4*)(g_xg + (size_t)g * Dd);
    dst[threadIdx.x] = src[threadIdx.x];
}

// ---------------- tf32 tensor-core grouped GEMM ----------------------------
// 128x128 block tile, 8 warps of 64x32, K-chunk 16 double-buffered cp.async.
// Scratch buffers selected INSIDE device code (never pass __device__ symbols
// as host-side kernel args — host shadow address + GB300 ATS = silent garbage).
template<int KD, int ND, bool DOGELU>
__global__ __launch_bounds__(256, 2) void k_gemm(const float* __restrict__ Wall,
                                                 const float* __restrict__ ball) {
    const float* Aall = DOGELU ? (const float*)g_xg : (const float*)g_y1;
    float*       Oall = DOGELU ? (float*)g_y1       : (float*)g_ffn;

    int e = blockIdx.x >> 5;
    int m0 = (blockIdx.x & 31) * 128;
    int cnt = g_cnt[e];
    if (m0 >= cnt) return;
    int goff = g_off[e];
    const float* A  = Aall + (size_t)goff * KD;
    const float* Bp = Wall + (size_t)e * KD * ND;
    const float* bias = ball + e * ND;
    int n0 = blockIdx.y * 128;

    __shared__ __align__(16) float As[2][128][20];   // K-chunk 16, pad 4
    __shared__ __align__(16) float Bs[2][16][136];   // 128 cols, pad 8

    uint32_t a_smem = (uint32_t)__cvta_generic_to_shared(&As[0][0][0]);
    uint32_t b_smem = (uint32_t)__cvta_generic_to_shared(&Bs[0][0][0]);
    const uint32_t ABUF = 128 * 20 * 4;
    const uint32_t BBUF = 16 * 136 * 4;

    int tid = threadIdx.x;
    int lane = tid & 31, warp = tid >> 5;
    int wm = warp & 1, wn = warp >> 1;     // warp tile: rows wm*64, cols wn*32
    int gid = lane >> 2, tg = lane & 3;

    float acc[4][4][4];
    #pragma unroll
    for (int mi = 0; mi < 4; mi++)
        #pragma unroll
        for (int ni = 0; ni < 4; ni++)
            #pragma unroll
            for (int q = 0; q < 4; q++) acc[mi][ni][q] = 0.f;

    const int NCH = KD / 16;

    auto load_chunk = [&](int c, int bufi) {
        int k0 = c * 16;
        #pragma unroll
        for (int i = tid; i < 512; i += 256) {
            int m = i >> 2, s = i & 3;
            int ok = (m0 + m < cnt);
            int mrow = ok ? (m0 + m) : 0;
            uint32_t dst = a_smem + bufi * ABUF + (uint32_t)(m * 20 + s * 4) * 4;
            cp_async16(dst, A + (size_t)mrow * KD + k0 + s * 4, ok ? 16 : 0);
        }
        #pragma unroll
        for (int i = tid; i < 512; i += 256) {
            int kk = i >> 5, s = i & 31;
            uint32_t dst = b_smem + bufi * BBUF + (uint32_t)(kk * 136 + s * 4) * 4;
            cp_async16(dst, Bp + (size_t)(k0 + kk) * ND + n0 + s * 4, 16);
        }
        cp_commit();
    };

    load_chunk(0, 0);
    int buf = 0;
    for (int c = 0; c < NCH; c++) {
        if (c + 1 < NCH) { load_chunk(c + 1, buf ^ 1); cp_wait<1>(); }
        else             { cp_wait<0>(); }
        __syncthreads();

        #pragma unroll
        for (int k8 = 0; k8 < 2; k8++) {
            int kc = k8 * 8;
            uint32_t bf[4][2];
            #pragma unroll
            for (int ni = 0; ni < 4; ni++) {
                int ncol = wn * 32 + ni * 8 + gid;
                bf[ni][0] = f2tf32(Bs[buf][kc + tg][ncol]);
                bf[ni][1] = f2tf32(Bs[buf][kc + tg + 4][ncol]);
            }
            #pragma unroll
            for (int mi = 0; mi < 4; mi++) {
                int r = wm * 64 + mi * 16 + gid;
                uint32_t af[4];
                af[0] = f2tf32(As[buf][r][kc + tg]);
                af[1] = f2tf32(As[buf][r + 8][kc + tg]);
                af[2] = f2tf32(As[buf][r][kc + tg + 4]);
                af[3] = f2tf32(As[buf][r + 8][kc + tg + 4]);
                #pragma unroll
                for (int ni = 0; ni < 4; ni++)
                    mma_tf32(acc[mi][ni], af, bf[ni]);
            }
        }
        __syncthreads();
        buf ^= 1;
    }

    // epilogue
    #pragma unroll
    for (int mi = 0; mi < 4; mi++) {
        int rloc0 = m0 + wm * 64 + mi * 16 + gid;
        #pragma unroll
        for (int half = 0; half < 2; half++) {
            int rloc = rloc0 + half * 8;
            if (rloc >= cnt) continue;
            int grow = goff + rloc;
            float* orow;
            float gate = 1.f;
            if (DOGELU) {
                orow = Oall + (size_t)grow * ND + n0;
            } else {
                int token = g_gtok[grow];
                gate = g_ggate[grow];
                orow = Oall + (size_t)token * ND + n0;
            }
            #pragma unroll
            for (int ni = 0; ni < 4; ni++) {
                int c = wn * 32 + ni * 8 + tg * 2;
                float v0 = acc[mi][ni][half * 2 + 0] + bias[n0 + c];
                float v1 = acc[mi][ni][half * 2 + 1] + bias[n0 + c + 1];
                if (DOGELU) { v0 = gelu_tanh(v0); v1 = gelu_tanh(v1); }
                else        { v0 *= gate; v1 *= gate; }
                orow[c] = v0; orow[c + 1] = v1;
            }
        }
    }
}

// v = clip(ffn @ Wv + bv, -3, 3)
__global__ void k_v(const float* __restrict__ Wv, const float* __restrict__ bv) {
    int t = blockIdx.x;
    __shared__ float red[256];
    int tid = threadIdx.x;
    float s = 0.f;
    for (int d = tid; d < Dd; d += 256) s += g_ffn[t * Dd + d] * Wv[d];
    red[tid] = s;
    __syncthreads();
    for (int st = 128; st; st >>= 1) {
        if (tid < st) red[tid] += red[tid + st];
        __syncthreads();
    }
    if (tid == 0) {
        float v = red[0] + bv[0];
        g_v[t] = fminf(fmaxf(v, -V_MAX), V_MAX);
    }
}

__global__ void k_thr() {
    __shared__ float s[Nn];
    int b = blockIdx.x, tid = threadIdx.x;
    for (int i = tid; i < Nn; i += 1024) s[i] = g_score[b * Nn + i];
    for (int k = 2; k <= Nn; k <<= 1) {
        for (int j = k >> 1; j > 0; j >>= 1) {
            __syncthreads();
            for (int i = tid; i < Nn; i += 1024) {
                int ixj = i ^ j;
                if (ixj > i) {
                    bool up = ((i & k) == 0);
                    float a = s[i], c = s[ixj];
                    if ((a > c) == up) { s[i] = c; s[ixj] = a; }
                }
            }
        }
    }
    __syncthreads();
    if (tid == 0) g_thr[b] = s[Nn - KKEEP];
}

__global__ void k_bk() {
    int id = threadIdx.x;
    if (id >= 2 * Bb) return;
    int b = id >> 1, dir = id & 1;
    float ar = 1e18f, ai = 0.f;
    if (dir == 0) {
        for (int i = 0; i < Nn; i++) {
            float dr = g_v[b * Nn + i];
            float den = ar * ar + ai * ai;
            float inv = 1.f / den;
            float nr = dr - ar * inv;
            float ni = -1.f + ai * inv;
            ar = nr; ai = ni;
            g_fr[b * Nn + i] = ar; g_fi[b * Nn + i] = ai;
        }
    } else {
        for (int i = Nn - 1; i >= 0; i--) {
            float dr = g_v[b * Nn + i];
            float den = ar * ar + ai * ai;
            float inv = 1.f / den;
            float nr = dr - ar * inv;
            float ni = -1.f + ai * inv;
            ar = nr; ai = ni;
            g_br[b * Nn + i] = ar; g_bi[b * Nn + i] = ai;
        }
    }
}

__global__ void k_out(const float* __restrict__ Wo, const float* __restrict__ bo,
                      const float* __restrict__ bk, float* __restrict__ out) {
    int t = blockIdx.x;
    int b = t >> 11;
    __shared__ float sfr, sfi, sbk;
    if (threadIdx.x == 0) {
        float v  = g_v[t];
        float cr = g_fr[t] + g_br[t] - v;
        float ci = g_fi[t] + g_bi[t] + 1.f;
        float den = cr * cr + ci * ci;
        float gr =  cr / den;
        float gi = -ci / den;
        float m = (g_score[t] >= g_thr[b]) ? 1.f : 0.f;
        sfr = fminf(fmaxf(gr * m, -FEAT_CLAMP), FEAT_CLAMP);
        sfi = fminf(fmaxf(gi * m, -FEAT_CLAMP), FEAT_CLAMP);
        sbk = bk[0];
    }
    __syncthreads();
    float fr = sfr, fi = sfi, s = sbk;
    for (int d = threadIdx.x; d < Dd; d += 192)
        out[(size_t)t * Dd + d] = g_ffn[t * Dd + d] + s * (fr * Wo[d] + fi * Wo[Dd + d] + bo[d]);
}

// ---------------- launch ---------------------------------------------------
extern "C" void kernel_launch(void* const* d_in, const int* in_sizes, int n_in,
                              void* d_out, int out_size) {
    const float* x   = (const float*)d_in[0];
    const float* Wg  = (const float*)d_in[1];
    const float* bg  = (const float*)d_in[2];
    const float* W1  = (const float*)d_in[3];
    const float* b1  = (const float*)d_in[4];
    const float* W2  = (const float*)d_in[5];
    const float* b2  = (const float*)d_in[6];
    const float* Wv  = (const float*)d_in[7];
    const float* bv  = (const float*)d_in[8];
    const float* Wm  = (const float*)d_in[9];
    const float* bm  = (const float*)d_in[10];
    const float* Wo  = (const float*)d_in[11];
    const float* bo  = (const float*)d_in[12];
    const float* bks = (const float*)d_in[13];
    float* out = (float*)d_out;

    k_zero<<<1, 32>>>();
    k_gate<<<Tt, 256>>>(x, Wg, bg, Wm, bm);
    k_off<<<1, 1>>>();
    k_gather<<<Tt, 192>>>(x);
    k_gemm<Dd, Hh, true ><<<dim3(Ee * 32, Hh / 128), 256>>>(W1, b1);
    k_gemm<Hh, Dd, false><<<dim3(Ee * 32, Dd / 128), 256>>>(W2, b2);
    k_v<<<Tt, 256>>>(Wv, bv);
    k_thr<<<Bb, 1024>>>();
    k_bk<<<1, 32>>>();
    k_out<<<Tt, 192>>>(Wo, bo, bks, out);
}

// round 6
// speedup vs baseline: 2.8769x; 1.1853x over previous
#include <cuda_runtime.h>
#include <cuda_fp16.h>
#include <math.h>
#include <stdint.h>

#define Bb 2
#define Nn 2048
#define Dd 768
#define Ee 8
#define Hh 3072
#define Tt (Bb*Nn)        // 4096
#define KKEEP 819         // int(2048*0.4)
#define V_MAX 3.0f
#define FEAT_CLAMP 10.0f

// ---------------- scratch (device globals; no allocation allowed) ----------
__device__ int   g_cnt[Ee];
__device__ int   g_off[Ee];
__device__ int   g_list[Ee * Tt];
__device__ int   g_gtok[Tt];
__device__ float g_ggate[Tt];
__device__ float g_gate[Tt];
__device__ float g_score[Tt];
__device__ __align__(256) __half g_xg[Tt * Dd];
__device__ __align__(256) __half g_y1[(size_t)Tt * Hh];
__device__ __align__(256) float  g_ffn[Tt * Dd];
__device__ __align__(256) __half g_wt1[(size_t)Ee * Dd * Hh];  // [e][n][k]
__device__ __align__(256) __half g_wt2[(size_t)Ee * Hh * Dd];  // [e][n][k]
__device__ float g_v[Tt];
__device__ float g_thr[Bb];
__device__ float g_fr[Tt], g_fi[Tt];
__device__ float g_br[Tt], g_bi[Tt];

// ---------------- PTX helpers ----------------------------------------------
__device__ __forceinline__ void cp_async16(uint32_t dst, const void* src, int szbytes) {
    asm volatile("cp.async.cg.shared.global [%0], [%1], 16, %2;\n"
                 :: "r"(dst), "l"(src), "r"(szbytes));
}
__device__ __forceinline__ void cp_commit() { asm volatile("cp.async.commit_group;"); }
template<int N> __device__ __forceinline__ void cp_wait() {
    asm volatile("cp.async.wait_group %0;" :: "n"(N));
}
__device__ __forceinline__ uint32_t smem_u32(const void* p) {
    return (uint32_t)__cvta_generic_to_shared(p);
}
// fp16 mma: m16n8k16, f32 accumulate
__device__ __forceinline__ void mma_f16(float* d, const uint32_t* a, const uint32_t* b) {
    asm volatile(
        "mma.sync.aligned.m16n8k16.row.col.f32.f16.f16.f32 "
        "{%0,%1,%2,%3}, {%4,%5,%6,%7}, {%8,%9}, {%0,%1,%2,%3};\n"
        : "+f"(d[0]), "+f"(d[1]), "+f"(d[2]), "+f"(d[3])
        : "r"(a[0]), "r"(a[1]), "r"(a[2]), "r"(a[3]), "r"(b[0]), "r"(b[1]));
}
__device__ __forceinline__ float gelu_tanh(float u) {
    return 0.5f * u * (1.f + tanhf(0.7978845608028654f * (u + 0.044715f * u * u * u)));
}

// ---------------- small kernels --------------------------------------------
__global__ void k_zero() {
    if (threadIdx.x < Ee) g_cnt[threadIdx.x] = 0;
}

__global__ void k_gate(const float* __restrict__ x, const float* __restrict__ Wg,
                       const float* __restrict__ bg, const float* __restrict__ Wm,
                       const float* __restrict__ bm) {
    int t = blockIdx.x;
    __shared__ float xs[Dd];
    __shared__ float red[256];
    __shared__ float logits[Ee];
    int tid = threadIdx.x;
    for (int d = tid; d < Dd; d += 256) xs[d] = x[t * Dd + d];
    __syncthreads();

    int w = tid >> 5, lane = tid & 31;
    float s = 0.f;
    for (int d = lane; d < Dd; d += 32) s += xs[d] * Wg[d * Ee + w];
    #pragma unroll
    for (int o = 16; o; o >>= 1) s += __shfl_xor_sync(0xffffffffu, s, o);
    if (lane == 0) logits[w] = s + bg[w];

    float sm = 0.f;
    for (int d = tid; d < Dd; d += 256) sm += xs[d] * Wm[d];
    red[tid] = sm;
    __syncthreads();
    for (int st = 128; st; st >>= 1) {
        if (tid < st) red[tid] += red[tid + st];
        __syncthreads();
    }
    if (tid == 0) {
        g_score[t] = 1.f / (1.f + expf(-(red[0] + bm[0])));
        float mx = logits[0]; int am = 0;
        #pragma unroll
        for (int e = 1; e < Ee; e++) if (logits[e] > mx) { mx = logits[e]; am = e; }
        float ssum = 0.f;
        #pragma unroll
        for (int e = 0; e < Ee; e++) ssum += expf(logits[e] - mx);
        g_gate[t] = 1.f / ssum;
        int pos = atomicAdd(&g_cnt[am], 1);
        g_list[am * Tt + pos] = t;
    }
}

__global__ void k_off() {
    int acc = 0;
    for (int e = 0; e < Ee; e++) { g_off[e] = acc; acc += g_cnt[e]; }
}

// gather x rows into expert-grouped buffer, converted to fp16
__global__ void k_gather(const float* __restrict__ x) {
    int g = blockIdx.x;
    int e = 0;
    #pragma unroll
    for (int q = 1; q < Ee; q++) if (g >= g_off[q]) e = q;
    int token = g_list[e * Tt + (g - g_off[e])];
    if (threadIdx.x == 0) { g_gtok[g] = token; g_ggate[g] = g_gate[token]; }
    int i = threadIdx.x;   // 0..191, 4 elems each
    float4 v = ((const float4*)(x + (size_t)token * Dd))[i];
    __half2* dst = (__half2*)(g_xg + (size_t)g * Dd);
    dst[i * 2]     = __floats2half2_rn(v.x, v.y);
    dst[i * 2 + 1] = __floats2half2_rn(v.z, v.w);
}

// transpose W[e][k][n] -> Wt[e][n][k] (fp16)
template<int KD, int ND, bool W1SEL>
__global__ void k_tr(const float* __restrict__ W) {
    __shared__ float tile[32][33];
    __half* Wt = W1SEL ? (__half*)g_wt1 : (__half*)g_wt2;
    int e = blockIdx.z;
    const float* Wp = W + (size_t)e * KD * ND;
    __half* Wq = Wt + (size_t)e * KD * ND;
    int n0 = blockIdx.x * 32, k0 = blockIdx.y * 32;
    int tx = threadIdx.x, ty = threadIdx.y;
    #pragma unroll
    for (int i = 0; i < 4; i++)
        tile[ty + i * 8][tx] = Wp[(size_t)(k0 + ty + i * 8) * ND + n0 + tx];
    __syncthreads();
    #pragma unroll
    for (int i = 0; i < 4; i++)
        Wq[(size_t)(n0 + ty + i * 8) * KD + k0 + tx] =
            __float2half_rn(tile[tx][ty + i * 8]);
}

// ---------------- fp16 tensor-core grouped GEMM ----------------------------
// 128x128 block tile, 8 warps of 64x32, K-chunk 32 double-buffered cp.async.
// A: grouped rows [cnt][KD] fp16 row-major; B: per-expert [ND][KD] fp16 (n-major).
// smem rows padded to 40 halfs -> LDS bank = (20*gid + tg) mod 32, conflict-free.
template<int KD, int ND, bool DOGELU>
__global__ __launch_bounds__(256, 2) void k_gemm(const float* __restrict__ ball) {
    const __half* Aall = DOGELU ? (const __half*)g_xg : (const __half*)g_y1;
    const __half* Wt   = DOGELU ? (const __half*)g_wt1 : (const __half*)g_wt2;

    int e = blockIdx.x >> 5;
    int m0 = (blockIdx.x & 31) * 128;
    int cnt = g_cnt[e];
    if (m0 >= cnt) return;
    int goff = g_off[e];
    const __half* Ap = Aall + (size_t)goff * KD;
    const __half* Bt = Wt + (size_t)e * KD * ND;
    const float* bias = ball + (size_t)e * ND;
    int n0 = blockIdx.y * 128;

    __shared__ __align__(16) __half As[2][128][40];
    __shared__ __align__(16) __half Bs[2][128][40];

    int tid = threadIdx.x;
    int lane = tid & 31, warp = tid >> 5;
    int wm = warp & 1, wn = warp >> 1;     // warp tile rows wm*64, cols wn*32
    int gid = lane >> 2, tg = lane & 3;

    float acc[4][4][4];
    #pragma unroll
    for (int mi = 0; mi < 4; mi++)
        #pragma unroll
        for (int ni = 0; ni < 4; ni++)
            #pragma unroll
            for (int q = 0; q < 4; q++) acc[mi][ni][q] = 0.f;

    const int NCH = KD / 32;

    auto load_chunk = [&](int c, int bufi) {
        int k0 = c * 32;
        #pragma unroll
        for (int i = tid; i < 512; i += 256) {      // A: 128 rows x 64B
            int m = i >> 2, seg = i & 3;
            int ok = (m0 + m < cnt);
            int mrow = ok ? (m0 + m) : 0;
            cp_async16(smem_u32(&As[bufi][m][seg * 8]),
                       Ap + (size_t)mrow * KD + k0 + seg * 8, ok ? 16 : 0);
        }
        #pragma unroll
        for (int i = tid; i < 512; i += 256) {      // B: 128 n-rows x 64B
            int n = i >> 2, seg = i & 3;
            cp_async16(smem_u32(&Bs[bufi][n][seg * 8]),
                       Bt + (size_t)(n0 + n) * KD + k0 + seg * 8, 16);
        }
        cp_commit();
    };

    load_chunk(0, 0);
    int buf = 0;
    for (int c = 0; c < NCH; c++) {
        if (c + 1 < NCH) { load_chunk(c + 1, buf ^ 1); cp_wait<1>(); }
        else             { cp_wait<0>(); }
        __syncthreads();

        #pragma unroll
        for (int k16 = 0; k16 < 2; k16++) {
            int kc = k16 * 16;
            uint32_t bf[4][2];
            #pragma unroll
            for (int ni = 0; ni < 4; ni++) {
                const __half* brow = &Bs[buf][wn * 32 + ni * 8 + gid][0];
                bf[ni][0] = *(const uint32_t*)(brow + kc + 2 * tg);
                bf[ni][1] = *(const uint32_t*)(brow + kc + 2 * tg + 8);
            }
            #pragma unroll
            for (int mi = 0; mi < 4; mi++) {
                const __half* arow = &As[buf][wm * 64 + mi * 16 + gid][0];
                uint32_t af[4];
                af[0] = *(const uint32_t*)(arow + kc + 2 * tg);
                af[1] = *(const uint32_t*)(arow + 8 * 40 + kc + 2 * tg);
                af[2] = *(const uint32_t*)(arow + kc + 2 * tg + 8);
                af[3] = *(const uint32_t*)(arow + 8 * 40 + kc + 2 * tg + 8);
                #pragma unroll
                for (int ni = 0; ni < 4; ni++)
                    mma_f16(acc[mi][ni], af, bf[ni]);
            }
        }
        __syncthreads();
        buf ^= 1;
    }

    // epilogue: c0=(gid,2tg) c1=(gid,2tg+1) c2=(gid+8,2tg) c3=(gid+8,2tg+1)
    #pragma unroll
    for (int mi = 0; mi < 4; mi++) {
        int rloc0 = m0 + wm * 64 + mi * 16 + gid;
        #pragma unroll
        for (int half = 0; half < 2; half++) {
            int rloc = rloc0 + half * 8;
            if (rloc >= cnt) continue;
            int grow = goff + rloc;
            if (DOGELU) {
                __half* orow = (__half*)g_y1 + (size_t)grow * ND + n0;
                #pragma unroll
                for (int ni = 0; ni < 4; ni++) {
                    int c = wn * 32 + ni * 8 + tg * 2;
                    float v0 = acc[mi][ni][half * 2 + 0] + bias[n0 + c];
                    float v1 = acc[mi][ni][half * 2 + 1] + bias[n0 + c + 1];
                    *(__half2*)(orow + c) =
                        __floats2half2_rn(gelu_tanh(v0), gelu_tanh(v1));
                }
            } else {
                int token = g_gtok[grow];
                float gate = g_ggate[grow];
                float* orow = g_ffn + (size_t)token * ND + n0;
                #pragma unroll
                for (int ni = 0; ni < 4; ni++) {
                    int c = wn * 32 + ni * 8 + tg * 2;
                    orow[c]     = gate * (acc[mi][ni][half * 2 + 0] + bias[n0 + c]);
                    orow[c + 1] = gate * (acc[mi][ni][half * 2 + 1] + bias[n0 + c + 1]);
                }
            }
        }
    }
}

// v = clip(ffn @ Wv + bv, -3, 3)
__global__ void k_v(const float* __restrict__ Wv, const float* __restrict__ bv) {
    int t = blockIdx.x;
    __shared__ float red[256];
    int tid = threadIdx.x;
    float s = 0.f;
    for (int d = tid; d < Dd; d += 256) s += g_ffn[t * Dd + d] * Wv[d];
    red[tid] = s;
    __syncthreads();
    for (int st = 128; st; st >>= 1) {
        if (tid < st) red[tid] += red[tid + st];
        __syncthreads();
    }
    if (tid == 0) {
        float v = red[0] + bv[0];
        g_v[t] = fminf(fmaxf(v, -V_MAX), V_MAX);
    }
}

__global__ void k_thr() {
    __shared__ float s[Nn];
    int b = blockIdx.x, tid = threadIdx.x;
    for (int i = tid; i < Nn; i += 1024) s[i] = g_score[b * Nn + i];
    for (int k = 2; k <= Nn; k <<= 1) {
        for (int j = k >> 1; j > 0; j >>= 1) {
            __syncthreads();
            for (int i = tid; i < Nn; i += 1024) {
                int ixj = i ^ j;
                if (ixj > i) {
                    bool up = ((i & k) == 0);
                    float a = s[i], c = s[ixj];
                    if ((a > c) == up) { s[i] = c; s[ixj] = a; }
                }
            }
        }
    }
    __syncthreads();
    if (tid == 0) g_thr[b] = s[Nn - KKEEP];
}

__global__ void k_bk() {
    int id = threadIdx.x;
    if (id >= 2 * Bb) return;
    int b = id >> 1, dir = id & 1;
    float ar = 1e18f, ai = 0.f;
    if (dir == 0) {
        for (int i = 0; i < Nn; i++) {
            float dr = g_v[b * Nn + i];
            float den = ar * ar + ai * ai;
            float inv = 1.f / den;
            float nr = dr - ar * inv;
            float ni = -1.f + ai * inv;
            ar = nr; ai = ni;
            g_fr[b * Nn + i] = ar; g_fi[b * Nn + i] = ai;
        }
    } else {
        for (int i = Nn - 1; i >= 0; i--) {
            float dr = g_v[b * Nn + i];
            float den = ar * ar + ai * ai;
            float inv = 1.f / den;
            float nr = dr - ar * inv;
            float ni = -1.f + ai * inv;
            ar = nr; ai = ni;
            g_br[b * Nn + i] = ar; g_bi[b * Nn + i] = ai;
        }
    }
}

__global__ void k_out(const float* __restrict__ Wo, const float* __restrict__ bo,
                      const float* __restrict__ bk, float* __restrict__ out) {
    int t = blockIdx.x;
    int b = t >> 11;
    __shared__ float sfr, sfi, sbk;
    if (threadIdx.x == 0) {
        float v  = g_v[t];
        float cr = g_fr[t] + g_br[t] - v;
        float ci = g_fi[t] + g_bi[t] + 1.f;
        float den = cr * cr + ci * ci;
        float gr =  cr / den;
        float gi = -ci / den;
        float m = (g_score[t] >= g_thr[b]) ? 1.f : 0.f;
        sfr = fminf(fmaxf(gr * m, -FEAT_CLAMP), FEAT_CLAMP);
        sfi = fminf(fmaxf(gi * m, -FEAT_CLAMP), FEAT_CLAMP);
        sbk = bk[0];
    }
    __syncthreads();
    float fr = sfr, fi = sfi, s = sbk;
    for (int d = threadIdx.x; d < Dd; d += 192)
        out[(size_t)t * Dd + d] = g_ffn[t * Dd + d] + s * (fr * Wo[d] + fi * Wo[Dd + d] + bo[d]);
}

// ---------------- launch ---------------------------------------------------
extern "C" void kernel_launch(void* const* d_in, const int* in_sizes, int n_in,
                              void* d_out, int out_size) {
    const float* x   = (const float*)d_in[0];
    const float* Wg  = (const float*)d_in[1];
    const float* bg  = (const float*)d_in[2];
    const float* W1  = (const float*)d_in[3];
    const float* b1  = (const float*)d_in[4];
    const float* W2  = (const float*)d_in[5];
    const float* b2  = (const float*)d_in[6];
    const float* Wv  = (const float*)d_in[7];
    const float* bv  = (const float*)d_in[8];
    const float* Wm  = (const float*)d_in[9];
    const float* bm  = (const float*)d_in[10];
    const float* Wo  = (const float*)d_in[11];
    const float* bo  = (const float*)d_in[12];
    const float* bks = (const float*)d_in[13];
    float* out = (float*)d_out;

    k_zero<<<1, 32>>>();
    k_gate<<<Tt, 256>>>(x, Wg, bg, Wm, bm);
    k_off<<<1, 1>>>();
    k_gather<<<Tt, 192>>>(x);
    k_tr<Dd, Hh, true ><<<dim3(Hh / 32, Dd / 32, Ee), dim3(32, 8)>>>(W1);
    k_tr<Hh, Dd, false><<<dim3(Dd / 32, Hh / 32, Ee), dim3(32, 8)>>>(W2);
    k_gemm<Dd, Hh, true ><<<dim3(Ee * 32, Hh / 128), 256>>>(b1);
    k_gemm<Hh, Dd, false><<<dim3(Ee * 32, Dd / 128), 256>>>(b2);
    k_v<<<Tt, 256>>>(Wv, bv);
    k_thr<<<Bb, 1024>>>();
    k_bk<<<1, 32>>>();
    k_out<<<Tt, 192>>>(Wo, bo, bks, out);
}

// round 7
// speedup vs baseline: 4.9197x; 1.7101x over previous
#include <cuda_runtime.h>
#include <cuda_fp16.h>
#include <math.h>
#include <stdint.h>

#define Bb 2
#define Nn 2048
#define Dd 768
#define Ee 8
#define Hh 3072
#define Tt (Bb*Nn)        // 4096
#define KKEEP 819         // int(2048*0.4)
#define V_MAX 3.0f
#define FEAT_CLAMP 10.0f

// ---------------- scratch (device globals; no allocation allowed) ----------
__device__ int   g_cnt[Ee];
__device__ int   g_off[Ee];
__device__ int   g_list[Ee * Tt];
__device__ int   g_gtok[Tt];
__device__ float g_ggate[Tt];
__device__ float g_gate[Tt];
__device__ float g_score[Tt];
__device__ __align__(256) __half g_xg[Tt * Dd];
__device__ __align__(256) __half g_y1[(size_t)Tt * Hh];
__device__ __align__(256) float  g_ffn[Tt * Dd];
__device__ __align__(256) __half g_wt1[(size_t)Ee * Dd * Hh];  // [e][n][k]
__device__ __align__(256) __half g_wt2[(size_t)Ee * Hh * Dd];  // [e][n][k]
__device__ float g_v[Tt];
__device__ float g_thr[Bb];
__device__ float g_fr[Tt], g_fi[Tt];
__device__ float g_br[Tt], g_bi[Tt];

// ---------------- PTX helpers ----------------------------------------------
__device__ __forceinline__ void cp_async16(uint32_t dst, const void* src, int szbytes) {
    asm volatile("cp.async.cg.shared.global [%0], [%1], 16, %2;\n"
                 :: "r"(dst), "l"(src), "r"(szbytes));
}
__device__ __forceinline__ void cp_commit() { asm volatile("cp.async.commit_group;"); }
template<int N> __device__ __forceinline__ void cp_wait() {
    asm volatile("cp.async.wait_group %0;" :: "n"(N));
}
__device__ __forceinline__ uint32_t smem_u32(const void* p) {
    return (uint32_t)__cvta_generic_to_shared(p);
}
__device__ __forceinline__ void ldsm_x4(uint32_t* r, uint32_t addr) {
    asm volatile("ldmatrix.sync.aligned.m8n8.x4.shared.b16 {%0,%1,%2,%3}, [%4];"
        : "=r"(r[0]), "=r"(r[1]), "=r"(r[2]), "=r"(r[3]) : "r"(addr));
}
__device__ __forceinline__ void mma_f16(float* d, const uint32_t* a, const uint32_t* b) {
    asm volatile(
        "mma.sync.aligned.m16n8k16.row.col.f32.f16.f16.f32 "
        "{%0,%1,%2,%3}, {%4,%5,%6,%7}, {%8,%9}, {%0,%1,%2,%3};\n"
        : "+f"(d[0]), "+f"(d[1]), "+f"(d[2]), "+f"(d[3])
        : "r"(a[0]), "r"(a[1]), "r"(a[2]), "r"(a[3]), "r"(b[0]), "r"(b[1]));
}
__device__ __forceinline__ float gelu_tanh(float u) {
    return 0.5f * u * (1.f + tanhf(0.7978845608028654f * (u + 0.044715f * u * u * u)));
}

// ---------------- small kernels --------------------------------------------
__global__ void k_gate(const float* __restrict__ x, const float* __restrict__ Wg,
                       const float* __restrict__ bg, const float* __restrict__ Wm,
                       const float* __restrict__ bm) {
    int t = blockIdx.x;
    __shared__ float xs[Dd];
    __shared__ float red[256];
    __shared__ float logits[Ee];
    int tid = threadIdx.x;
    for (int d = tid; d < Dd; d += 256) xs[d] = x[t * Dd + d];
    __syncthreads();

    int w = tid >> 5, lane = tid & 31;
    float s = 0.f;
    for (int d = lane; d < Dd; d += 32) s += xs[d] * Wg[d * Ee + w];
    #pragma unroll
    for (int o = 16; o; o >>= 1) s += __shfl_xor_sync(0xffffffffu, s, o);
    if (lane == 0) logits[w] = s + bg[w];

    float sm = 0.f;
    for (int d = tid; d < Dd; d += 256) sm += xs[d] * Wm[d];
    red[tid] = sm;
    __syncthreads();
    for (int st = 128; st; st >>= 1) {
        if (tid < st) red[tid] += red[tid + st];
        __syncthreads();
    }
    if (tid == 0) {
        g_score[t] = 1.f / (1.f + expf(-(red[0] + bm[0])));
        float mx = logits[0]; int am = 0;
        #pragma unroll
        for (int e = 1; e < Ee; e++) if (logits[e] > mx) { mx = logits[e]; am = e; }
        float ssum = 0.f;
        #pragma unroll
        for (int e = 0; e < Ee; e++) ssum += expf(logits[e] - mx);
        g_gate[t] = 1.f / ssum;
        int pos = atomicAdd(&g_cnt[am], 1);
        g_list[am * Tt + pos] = t;
    }
}

__global__ void k_off() {
    int acc = 0;
    for (int e = 0; e < Ee; e++) { g_off[e] = acc; acc += g_cnt[e]; }
}

// gather x rows into expert-grouped buffer, converted to fp16
__global__ void k_gather(const float* __restrict__ x) {
    int g = blockIdx.x;
    int e = 0;
    #pragma unroll
    for (int q = 1; q < Ee; q++) if (g >= g_off[q]) e = q;
    int token = g_list[e * Tt + (g - g_off[e])];
    if (threadIdx.x == 0) { g_gtok[g] = token; g_ggate[g] = g_gate[token]; }
    int i = threadIdx.x;   // 0..191, 4 elems each
    float4 v = ((const float4*)(x + (size_t)token * Dd))[i];
    __half2* dst = (__half2*)(g_xg + (size_t)g * Dd);
    dst[i * 2]     = __floats2half2_rn(v.x, v.y);
    dst[i * 2 + 1] = __floats2half2_rn(v.z, v.w);
}

// transpose W[e][k][n] -> Wt[e][n][k] (fp16)
template<int KD, int ND, bool W1SEL>
__global__ void k_tr(const float* __restrict__ W) {
    __shared__ float tile[32][33];
    __half* Wt = W1SEL ? (__half*)g_wt1 : (__half*)g_wt2;
    int e = blockIdx.z;
    const float* Wp = W + (size_t)e * KD * ND;
    __half* Wq = Wt + (size_t)e * KD * ND;
    int n0 = blockIdx.x * 32, k0 = blockIdx.y * 32;
    int tx = threadIdx.x, ty = threadIdx.y;
    #pragma unroll
    for (int i = 0; i < 4; i++)
        tile[ty + i * 8][tx] = Wp[(size_t)(k0 + ty + i * 8) * ND + n0 + tx];
    __syncthreads();
    #pragma unroll
    for (int i = 0; i < 4; i++)
        Wq[(size_t)(n0 + ty + i * 8) * KD + k0 + tx] =
            __float2half_rn(tile[tx][ty + i * 8]);
}

// ---------------- fp16 tensor-core grouped GEMM ----------------------------
// 128x128 tile, 8 warps of 64x32, K-chunk 32, 3-stage cp.async, ldmatrix.x4.
// A: grouped rows [cnt][KD] fp16; B: [ND][KD] fp16 (n-major, pre-transposed).
// smem row = 40 halfs (80B): ldmatrix 8-row phases hit all banks once.
#define GST 3
#define GSMEM (GST * 2 * 128 * 40 * 2)   // 61440 bytes

template<int KD, int ND, bool DOGELU>
__global__ __launch_bounds__(256, 2) void k_gemm(const float* __restrict__ ball) {
    const __half* Aall = DOGELU ? (const __half*)g_xg : (const __half*)g_y1;
    const __half* Wt   = DOGELU ? (const __half*)g_wt1 : (const __half*)g_wt2;

    int e = blockIdx.x >> 5;
    int m0 = (blockIdx.x & 31) * 128;
    int cnt = g_cnt[e];
    if (m0 >= cnt) return;
    int goff = g_off[e];
    const __half* Ap = Aall + (size_t)goff * KD;
    const __half* Bt = Wt + (size_t)e * KD * ND;
    const float* bias = ball + (size_t)e * ND;
    int n0 = blockIdx.y * 128;

    extern __shared__ __align__(16) __half sh[];
    // stage s: A at sh + s*10240, B at sh + s*10240 + 5120 (units: halfs)

    int tid = threadIdx.x;
    int lane = tid & 31, warp = tid >> 5;
    int wm = warp & 1, wn = warp >> 1;     // warp tile rows wm*64, cols wn*32
    int gid = lane >> 2, tg = lane & 3;

    float acc[4][4][4];
    #pragma unroll
    for (int mi = 0; mi < 4; mi++)
        #pragma unroll
        for (int ni = 0; ni < 4; ni++)
            #pragma unroll
            for (int q = 0; q < 4; q++) acc[mi][ni][q] = 0.f;

    const int NCH = KD / 32;

    auto load_chunk = [&](int c, int s) {
        int k0 = c * 32;
        __half* a = sh + s * 10240;
        __half* b = sh + s * 10240 + 5120;
        #pragma unroll
        for (int i = tid; i < 512; i += 256) {      // A: 128 rows x 64B
            int m = i >> 2, seg = i & 3;
            int ok = (m0 + m < cnt);
            int mrow = ok ? (m0 + m) : 0;
            cp_async16(smem_u32(a + m * 40 + seg * 8),
                       Ap + (size_t)mrow * KD + k0 + seg * 8, ok ? 16 : 0);
        }
        #pragma unroll
        for (int i = tid; i < 512; i += 256) {      // B: 128 n-rows x 64B
            int n = i >> 2, seg = i & 3;
            cp_async16(smem_u32(b + (size_t)n * 40 + seg * 8),
                       Bt + (size_t)(n0 + n) * KD + k0 + seg * 8, 16);
        }
        cp_commit();
    };

    load_chunk(0, 0);
    load_chunk(1, 1);
    // ldmatrix lane roles (computed once)
    int arow = wm * 64 + (lane & 15);
    int acol = (lane >> 4) * 8;
    int brow = wn * 32 + (lane & 7) + (lane >> 4) * 8;
    int bcol = ((lane >> 3) & 1) * 8;

    for (int c = 0; c < NCH; c++) {
        if (c + 2 < NCH) { load_chunk(c + 2, (c + 2) % GST); cp_wait<2>(); }
        else if (c + 1 < NCH) { cp_wait<1>(); }
        else { cp_wait<0>(); }
        __syncthreads();

        int s = c % GST;
        const __half* a = sh + s * 10240;
        const __half* b = sh + s * 10240 + 5120;

        #pragma unroll
        for (int k16 = 0; k16 < 2; k16++) {
            int kc = k16 * 16;
            uint32_t af[4][4];
            #pragma unroll
            for (int mi = 0; mi < 4; mi++)
                ldsm_x4(af[mi], smem_u32(a + (arow + mi * 16) * 40 + kc + acol));
            uint32_t bf[4][2];
            #pragma unroll
            for (int p = 0; p < 2; p++) {
                uint32_t r[4];
                ldsm_x4(r, smem_u32(b + (brow + p * 16) * 40 + kc + bcol));
                bf[2 * p][0] = r[0]; bf[2 * p][1] = r[1];
                bf[2 * p + 1][0] = r[2]; bf[2 * p + 1][1] = r[3];
            }
            #pragma unroll
            for (int mi = 0; mi < 4; mi++)
                #pragma unroll
                for (int ni = 0; ni < 4; ni++)
                    mma_f16(acc[mi][ni], af[mi], bf[ni]);
        }
        __syncthreads();
    }

    // epilogue: c0=(gid,2tg) c1=(gid,2tg+1) c2=(gid+8,2tg) c3=(gid+8,2tg+1)
    #pragma unroll
    for (int mi = 0; mi < 4; mi++) {
        int rloc0 = m0 + wm * 64 + mi * 16 + gid;
        #pragma unroll
        for (int half = 0; half < 2; half++) {
            int rloc = rloc0 + half * 8;
            if (rloc >= cnt) continue;
            int grow = goff + rloc;
            if (DOGELU) {
                __half* orow = (__half*)g_y1 + (size_t)grow * ND + n0;
                #pragma unroll
                for (int ni = 0; ni < 4; ni++) {
                    int c = wn * 32 + ni * 8 + tg * 2;
                    float v0 = acc[mi][ni][half * 2 + 0] + bias[n0 + c];
                    float v1 = acc[mi][ni][half * 2 + 1] + bias[n0 + c + 1];
                    *(__half2*)(orow + c) =
                        __floats2half2_rn(gelu_tanh(v0), gelu_tanh(v1));
                }
            } else {
                int token = g_gtok[grow];
                float gate = g_ggate[grow];
                float* orow = g_ffn + (size_t)token * ND + n0;
                #pragma unroll
                for (int ni = 0; ni < 4; ni++) {
                    int c = wn * 32 + ni * 8 + tg * 2;
                    orow[c]     = gate * (acc[mi][ni][half * 2 + 0] + bias[n0 + c]);
                    orow[c + 1] = gate * (acc[mi][ni][half * 2 + 1] + bias[n0 + c + 1]);
                }
            }
        }
    }
}

// v = clip(ffn @ Wv + bv, -3, 3); also resets g_cnt for next graph replay
__global__ void k_v(const float* __restrict__ Wv, const float* __restrict__ bv) {
    int t = blockIdx.x;
    int tid = threadIdx.x;
    if (blockIdx.x == 0 && tid < Ee) g_cnt[tid] = 0;
    __shared__ float red[256];
    float s = 0.f;
    for (int d = tid; d < Dd; d += 256) s += g_ffn[t * Dd + d] * Wv[d];
    red[tid] = s;
    __syncthreads();
    for (int st = 128; st; st >>= 1) {
        if (tid < st) red[tid] += red[tid + st];
        __syncthreads();
    }
    if (tid == 0) {
        float v = red[0] + bv[0];
        g_v[t] = fminf(fmaxf(v, -V_MAX), V_MAX);
    }
}

__global__ void k_thr() {
    __shared__ float s[Nn];
    int b = blockIdx.x, tid = threadIdx.x;
    for (int i = tid; i < Nn; i += 1024) s[i] = g_score[b * Nn + i];
    for (int k = 2; k <= Nn; k <<= 1) {
        for (int j = k >> 1; j > 0; j >>= 1) {
            __syncthreads();
            for (int i = tid; i < Nn; i += 1024) {
                int ixj = i ^ j;
                if (ixj > i) {
                    bool up = ((i & k) == 0);
                    float a = s[i], c = s[ixj];
                    if ((a > c) == up) { s[i] = c; s[ixj] = a; }
                }
            }
        }
    }
    __syncthreads();
    if (tid == 0) g_thr[b] = s[Nn - KKEEP];
}

// ---------------- parallel BK continued fraction ---------------------------
// a_i = d_i - 1/a_{i-1} is Mobius: M_i = [[d_i,-1],[1,0]] (complex 2x2).
// 1 warp per (batch, dir): lane composes 64 normalized matrices, KS shuffle
// scan, then replays the exact serial recursion from its incoming value.
struct CM2 { float r00,i00,r01,i01,r10,i10,r11,i11; };
__device__ __forceinline__ CM2 cm2_mul(const CM2& A, const CM2& B) {
    CM2 C;
    C.r00 = A.r00*B.r00 - A.i00*B.i00 + A.r01*B.r10 - A.i01*B.i10;
    C.i00 = A.r00*B.i00 + A.i00*B.r00 + A.r01*B.i10 + A.i01*B.r10;
    C.r01 = A.r00*B.r01 - A.i00*B.i01 + A.r01*B.r11 - A.i01*B.i11;
    C.i01 = A.r00*B.i01 + A.i00*B.r01 + A.r01*B.i11 + A.i01*B.r11;
    C.r10 = A.r10*B.r00 - A.i10*B.i00 + A.r11*B.r10 - A.i11*B.i10;
    C.i10 = A.r10*B.i00 + A.i10*B.r00 + A.r11*B.i10 + A.i11*B.r10;
    C.r11 = A.r10*B.r01 - A.i10*B.i01 + A.r11*B.r11 - A.i11*B.i11;
    C.i11 = A.r10*B.i01 + A.i10*B.r01 + A.r11*B.i11 + A.i11*B.r11;
    return C;
}
__device__ __forceinline__ void cm2_norm(CM2& A) {
    float mx = fmaxf(fmaxf(fabsf(A.r00)+fabsf(A.i00), fabsf(A.r01)+fabsf(A.i01)),
                     fmaxf(fabsf(A.r10)+fabsf(A.i10), fabsf(A.r11)+fabsf(A.i11)));
    float sc = 1.f / fmaxf(mx, 1e-30f);
    A.r00*=sc; A.i00*=sc; A.r01*=sc; A.i01*=sc;
    A.r10*=sc; A.i10*=sc; A.r11*=sc; A.i11*=sc;
}
__device__ __forceinline__ CM2 cm2_shfl_up(const CM2& A, int off) {
    CM2 B;
    B.r00 = __shfl_up_sync(0xffffffffu, A.r00, off);
    B.i00 = __shfl_up_sync(0xffffffffu, A.i00, off);
    B.r01 = __shfl_up_sync(0xffffffffu, A.r01, off);
    B.i01 = __shfl_up_sync(0xffffffffu, A.i01, off);
    B.r10 = __shfl_up_sync(0xffffffffu, A.r10, off);
    B.i10 = __shfl_up_sync(0xffffffffu, A.i10, off);
    B.r11 = __shfl_up_sync(0xffffffffu, A.r11, off);
    B.i11 = __shfl_up_sync(0xffffffffu, A.i11, off);
    return B;
}

__global__ void k_bk() {
    int b = blockIdx.x >> 1, dir = blockIdx.x & 1;
    int lane = threadIdx.x;
    const int CH = Nn / 32;   // 64
    const float* vv = g_v + b * Nn;

    // local matrix product (later steps multiply on the left)
    CM2 P = {1,0, 0,0, 0,0, 1,0};
    for (int j = 0; j < CH; j++) {
        int idx = lane * CH + j;
        int pos = dir ? (Nn - 1 - idx) : idx;
        float dr = vv[pos], di = -1.f;
        CM2 M = {dr, di, -1.f, 0.f, 1.f, 0.f, 0.f, 0.f};
        P = cm2_mul(M, P);
        cm2_norm(P);
    }
    // inclusive scan: S_L = P_L * ... * P_0
    CM2 S = P;
    #pragma unroll
    for (int off = 1; off < 32; off <<= 1) {
        CM2 O = cm2_shfl_up(S, off);
        if (lane >= off) { S = cm2_mul(S, O); cm2_norm(S); }
    }
    // exclusive prefix
    CM2 E = cm2_shfl_up(S, 1);
    float ar, ai;
    if (lane == 0) { ar = 1e18f; ai = 0.f; }
    else {
        // a_in = (E00*a0 + E01) / (E10*a0 + E11), a0 = 1e18
        float nr = E.r00 * 1e18f + E.r01, ni = E.i00 * 1e18f + E.i01;
        float qr = E.r10 * 1e18f + E.r11, qi = E.i10 * 1e18f + E.i11;
        float den = qr * qr + qi * qi;
        if (den < 1e-36f) { ar = 1e18f; ai = 0.f; }
        else { ar = (nr * qr + ni * qi) / den; ai = (ni * qr - nr * qi) / den; }
    }
    // serial replay (exact reference recursion)
    float* outr = dir ? g_br : g_fr;
    float* outi = dir ? g_bi : g_fi;
    for (int j = 0; j < CH; j++) {
        int idx = lane * CH + j;
        int pos = dir ? (Nn - 1 - idx) : idx;
        float dr = vv[pos];
        float den = ar * ar + ai * ai;
        float inv = 1.f / den;
        float nr = dr - ar * inv;
        float ni = -1.f + ai * inv;
        ar = nr; ai = ni;
        outr[b * Nn + pos] = ar; outi[b * Nn + pos] = ai;
    }
}

__global__ void k_out(const float* __restrict__ Wo, const float* __restrict__ bo,
                      const float* __restrict__ bk, float* __restrict__ out) {
    int t = blockIdx.x;
    int b = t >> 11;
    __shared__ float sfr, sfi, sbk;
    if (threadIdx.x == 0) {
        float v  = g_v[t];
        float cr = g_fr[t] + g_br[t] - v;
        float ci = g_fi[t] + g_bi[t] + 1.f;
        float den = cr * cr + ci * ci;
        float gr =  cr / den;
        float gi = -ci / den;
        float m = (g_score[t] >= g_thr[b]) ? 1.f : 0.f;
        sfr = fminf(fmaxf(gr * m, -FEAT_CLAMP), FEAT_CLAMP);
        sfi = fminf(fmaxf(gi * m, -FEAT_CLAMP), FEAT_CLAMP);
        sbk = bk[0];
    }
    __syncthreads();
    float fr = sfr, fi = sfi, s = sbk;
    for (int d = threadIdx.x; d < Dd; d += 192)
        out[(size_t)t * Dd + d] = g_ffn[t * Dd + d] + s * (fr * Wo[d] + fi * Wo[Dd + d] + bo[d]);
}

// ---------------- launch ---------------------------------------------------
extern "C" void kernel_launch(void* const* d_in, const int* in_sizes, int n_in,
                              void* d_out, int out_size) {
    const float* x   = (const float*)d_in[0];
    const float* Wg  = (const float*)d_in[1];
    const float* bg  = (const float*)d_in[2];
    const float* W1  = (const float*)d_in[3];
    const float* b1  = (const float*)d_in[4];
    const float* W2  = (const float*)d_in[5];
    const float* b2  = (const float*)d_in[6];
    const float* Wv  = (const float*)d_in[7];
    const float* bv  = (const float*)d_in[8];
    const float* Wm  = (const float*)d_in[9];
    const float* bm  = (const float*)d_in[10];
    const float* Wo  = (const float*)d_in[11];
    const float* bo  = (const float*)d_in[12];
    const float* bks = (const float*)d_in[13];
    float* out = (float*)d_out;

    static int attr_done = 0;
    if (!attr_done) {
        cudaFuncSetAttribute(k_gemm<Dd, Hh, true >,
                             cudaFuncAttributeMaxDynamicSharedMemorySize, GSMEM);
        cudaFuncSetAttribute(k_gemm<Hh, Dd, false>,
                             cudaFuncAttributeMaxDynamicSharedMemorySize, GSMEM);
        attr_done = 1;
    }

    k_gate<<<Tt, 256>>>(x, Wg, bg, Wm, bm);
    k_off<<<1, 1>>>();
    k_gather<<<Tt, 192>>>(x);
    k_tr<Dd, Hh, true ><<<dim3(Hh / 32, Dd / 32, Ee), dim3(32, 8)>>>(W1);
    k_tr<Hh, Dd, false><<<dim3(Dd / 32, Hh / 32, Ee), dim3(32, 8)>>>(W2);
    k_gemm<Dd, Hh, true ><<<dim3(Ee * 32, Hh / 128), 256, GSMEM>>>(b1);
    k_gemm<Hh, Dd, false><<<dim3(Ee * 32, Dd / 128), 256, GSMEM>>>(b2);
    k_v<<<Tt, 256>>>(Wv, bv);
    k_thr<<<Bb, 1024>>>();
    k_bk<<<2 * Bb, 32>>>();
    k_out<<<Tt, 192>>>(Wo, bo, bks, out);
}

// round 8
// speedup vs baseline: 5.4338x; 1.1045x over previous
#include <cuda_runtime.h>
#include <cuda_fp16.h>
#include <math.h>
#include <stdint.h>

#define Bb 2
#define Nn 2048
#define Dd 768
#define Ee 8
#define Hh 3072
#define Tt (Bb*Nn)        // 4096
#define KKEEP 819         // int(2048*0.4)
#define V_MAX 3.0f
#define FEAT_CLAMP 10.0f

// ---------------- scratch (device globals; no allocation allowed) ----------
__device__ int   g_cnt[Ee];
__device__ int   g_off[Ee];
__device__ int   g_list[Ee * Tt];
__device__ int   g_gtok[Tt];
__device__ float g_ggate[Tt];
__device__ float g_gate[Tt];
__device__ float g_score[Tt];
__device__ __align__(256) __half g_xg[Tt * Dd];
__device__ __align__(256) __half g_y1[(size_t)Tt * Hh];
__device__ __align__(256) float  g_ffn[Tt * Dd];
__device__ __align__(256) __half g_wt1[(size_t)Ee * Dd * Hh];  // [e][n][k]
__device__ __align__(256) __half g_wt2[(size_t)Ee * Hh * Dd];  // [e][n][k]
__device__ float g_vpart[Tt * 24];
__device__ float g_v[Tt];
__device__ float g_thr[Bb];
__device__ float g_fr[Tt], g_fi[Tt];
__device__ float g_br[Tt], g_bi[Tt];

// ---------------- PTX helpers ----------------------------------------------
__device__ __forceinline__ void cp_async16(uint32_t dst, const void* src, int szbytes) {
    asm volatile("cp.async.cg.shared.global [%0], [%1], 16, %2;\n"
                 :: "r"(dst), "l"(src), "r"(szbytes));
}
__device__ __forceinline__ void cp_commit() { asm volatile("cp.async.commit_group;"); }
template<int N> __device__ __forceinline__ void cp_wait() {
    asm volatile("cp.async.wait_group %0;" :: "n"(N));
}
__device__ __forceinline__ uint32_t smem_u32(const void* p) {
    return (uint32_t)__cvta_generic_to_shared(p);
}
__device__ __forceinline__ void ldsm_x4(uint32_t* r, uint32_t addr) {
    asm volatile("ldmatrix.sync.aligned.m8n8.x4.shared.b16 {%0,%1,%2,%3}, [%4];"
        : "=r"(r[0]), "=r"(r[1]), "=r"(r[2]), "=r"(r[3]) : "r"(addr));
}
__device__ __forceinline__ void mma_f16(float* d, const uint32_t* a, const uint32_t* b) {
    asm volatile(
        "mma.sync.aligned.m16n8k16.row.col.f32.f16.f16.f32 "
        "{%0,%1,%2,%3}, {%4,%5,%6,%7}, {%8,%9}, {%0,%1,%2,%3};\n"
        : "+f"(d[0]), "+f"(d[1]), "+f"(d[2]), "+f"(d[3])
        : "r"(a[0]), "r"(a[1]), "r"(a[2]), "r"(a[3]), "r"(b[0]), "r"(b[1]));
}
__device__ __forceinline__ float gelu_tanh(float u) {
    return 0.5f * u * (1.f + tanhf(0.7978845608028654f * (u + 0.044715f * u * u * u)));
}

// ---------------- small kernels --------------------------------------------
__global__ void k_gate(const float* __restrict__ x, const float* __restrict__ Wg,
                       const float* __restrict__ bg, const float* __restrict__ Wm,
                       const float* __restrict__ bm) {
    int t = blockIdx.x;
    __shared__ float xs[Dd];
    __shared__ float wsum[8];
    __shared__ float logits[Ee];
    int tid = threadIdx.x;
    for (int d = tid; d < Dd; d += 256) xs[d] = x[t * Dd + d];
    __syncthreads();

    int w = tid >> 5, lane = tid & 31;
    float s = 0.f;
    for (int d = lane; d < Dd; d += 32) s += xs[d] * Wg[d * Ee + w];
    #pragma unroll
    for (int o = 16; o; o >>= 1) s += __shfl_xor_sync(0xffffffffu, s, o);
    if (lane == 0) logits[w] = s + bg[w];

    float sm = 0.f;
    for (int d = tid; d < Dd; d += 256) sm += xs[d] * Wm[d];
    #pragma unroll
    for (int o = 16; o; o >>= 1) sm += __shfl_xor_sync(0xffffffffu, sm, o);
    if (lane == 0) wsum[w] = sm;
    __syncthreads();

    if (tid == 0) {
        float tot = 0.f;
        #pragma unroll
        for (int q = 0; q < 8; q++) tot += wsum[q];
        g_score[t] = 1.f / (1.f + expf(-(tot + bm[0])));
        float mx = logits[0]; int am = 0;
        #pragma unroll
        for (int e = 1; e < Ee; e++) if (logits[e] > mx) { mx = logits[e]; am = e; }
        float ssum = 0.f;
        #pragma unroll
        for (int e = 0; e < Ee; e++) ssum += expf(logits[e] - mx);
        g_gate[t] = 1.f / ssum;
        int pos = atomicAdd(&g_cnt[am], 1);
        g_list[am * Tt + pos] = t;
    }
}

__global__ void k_off() {
    int acc = 0;
    for (int e = 0; e < Ee; e++) { g_off[e] = acc; acc += g_cnt[e]; }
}

// gather x rows into expert-grouped buffer, converted to fp16
__global__ void k_gather(const float* __restrict__ x) {
    int g = blockIdx.x;
    int e = 0;
    #pragma unroll
    for (int q = 1; q < Ee; q++) if (g >= g_off[q]) e = q;
    int token = g_list[e * Tt + (g - g_off[e])];
    if (threadIdx.x == 0) { g_gtok[g] = token; g_ggate[g] = g_gate[token]; }
    int i = threadIdx.x;   // 0..191, 4 elems each
    float4 v = ((const float4*)(x + (size_t)token * Dd))[i];
    __half2* dst = (__half2*)(g_xg + (size_t)g * Dd);
    dst[i * 2]     = __floats2half2_rn(v.x, v.y);
    dst[i * 2 + 1] = __floats2half2_rn(v.z, v.w);
}

// transpose W[e][k][n] fp32 -> Wt[e][n][k] fp16; 64k x 32n tile, half2 writes
template<int KD, int ND, bool W1SEL>
__global__ void k_tr(const float* __restrict__ W) {
    __shared__ float tile[64][33];
    __half* Wt = W1SEL ? (__half*)g_wt1 : (__half*)g_wt2;
    int e = blockIdx.z;
    const float* Wp = W + (size_t)e * KD * ND;
    __half* Wq = Wt + (size_t)e * KD * ND;
    int n0 = blockIdx.x * 32, k0 = blockIdx.y * 64;
    int tx = threadIdx.x, ty = threadIdx.y;   // (32, 8)
    #pragma unroll
    for (int i = 0; i < 8; i++) {
        int kl = i * 8 + ty;
        tile[kl][tx] = Wp[(size_t)(k0 + kl) * ND + n0 + tx];
    }
    __syncthreads();
    #pragma unroll
    for (int i = 0; i < 4; i++) {
        int nl = i * 8 + ty;
        __half2 h = __floats2half2_rn(tile[2 * tx][nl], tile[2 * tx + 1][nl]);
        *(__half2*)(Wq + (size_t)(n0 + nl) * KD + k0 + 2 * tx) = h;
    }
}

// ---------------- fp16 tensor-core grouped GEMM ----------------------------
// 128x128 tile, 8 warps of 64x32, K-chunk 32, 3-stage cp.async, ldmatrix.x4.
// ONE __syncthreads per chunk: wait -> sync -> issue load(c+2) -> compute(c).
// GEMM2 epilogue fuses the v = ffn . Wv partial dot (deterministic partials).
#define GST 3
#define GSMEM (GST * 2 * 128 * 40 * 2)   // 61440 bytes

template<int KD, int ND, bool DOGELU>
__global__ __launch_bounds__(256, 2) void k_gemm(const float* __restrict__ ball,
                                                 const float* __restrict__ Wv) {
    const __half* Aall = DOGELU ? (const __half*)g_xg : (const __half*)g_y1;
    const __half* Wt   = DOGELU ? (const __half*)g_wt1 : (const __half*)g_wt2;

    int e = blockIdx.x >> 5;
    int m0 = (blockIdx.x & 31) * 128;
    int cnt = g_cnt[e];
    if (m0 >= cnt) return;
    int goff = g_off[e];
    const __half* Ap = Aall + (size_t)goff * KD;
    const __half* Bt = Wt + (size_t)e * KD * ND;
    const float* bias = ball + (size_t)e * ND;
    int n0 = blockIdx.y * 128;

    extern __shared__ __align__(16) __half sh[];

    int tid = threadIdx.x;
    int lane = tid & 31, warp = tid >> 5;
    int wm = warp & 1, wn = warp >> 1;     // warp tile rows wm*64, cols wn*32
    int gid = lane >> 2, tg = lane & 3;

    float acc[4][4][4];
    #pragma unroll
    for (int mi = 0; mi < 4; mi++)
        #pragma unroll
        for (int ni = 0; ni < 4; ni++)
            #pragma unroll
            for (int q = 0; q < 4; q++) acc[mi][ni][q] = 0.f;

    const int NCH = KD / 32;

    auto load_chunk = [&](int c, int s) {
        int k0 = c * 32;
        __half* a = sh + s * 10240;
        __half* b = sh + s * 10240 + 5120;
        #pragma unroll
        for (int i = tid; i < 512; i += 256) {      // A: 128 rows x 64B
            int m = i >> 2, seg = i & 3;
            int ok = (m0 + m < cnt);
            int mrow = ok ? (m0 + m) : 0;
            cp_async16(smem_u32(a + m * 40 + seg * 8),
                       Ap + (size_t)mrow * KD + k0 + seg * 8, ok ? 16 : 0);
        }
        #pragma unroll
        for (int i = tid; i < 512; i += 256) {      // B: 128 n-rows x 64B
            int n = i >> 2, seg = i & 3;
            cp_async16(smem_u32(b + (size_t)n * 40 + seg * 8),
                       Bt + (size_t)(n0 + n) * KD + k0 + seg * 8, 16);
        }
        cp_commit();
    };

    load_chunk(0, 0);
    load_chunk(1, 1);
    int arow = wm * 64 + (lane & 15);
    int acol = (lane >> 4) * 8;
    int brow = wn * 32 + (lane & 7) + (lane >> 4) * 8;
    int bcol = ((lane >> 3) & 1) * 8;

    for (int c = 0; c < NCH; c++) {
        if (c + 2 < NCH) { cp_wait<1>(); } else { cp_wait<0>(); }
        __syncthreads();   // data ready for all; stage (c+2)%3 free for reuse
        if (c + 2 < NCH) load_chunk(c + 2, (c + 2) % GST);

        int s = c % GST;
        const __half* a = sh + s * 10240;
        const __half* b = sh + s * 10240 + 5120;

        #pragma unroll
        for (int k16 = 0; k16 < 2; k16++) {
            int kc = k16 * 16;
            uint32_t af[4][4];
            #pragma unroll
            for (int mi = 0; mi < 4; mi++)
                ldsm_x4(af[mi], smem_u32(a + (arow + mi * 16) * 40 + kc + acol));
            uint32_t bf[4][2];
            #pragma unroll
            for (int p = 0; p < 2; p++) {
                uint32_t r[4];
                ldsm_x4(r, smem_u32(b + (brow + p * 16) * 40 + kc + bcol));
                bf[2 * p][0] = r[0]; bf[2 * p][1] = r[1];
                bf[2 * p + 1][0] = r[2]; bf[2 * p + 1][1] = r[3];
            }
            #pragma unroll
            for (int mi = 0; mi < 4; mi++)
                #pragma unroll
                for (int ni = 0; ni < 4; ni++)
                    mma_f16(acc[mi][ni], af[mi], bf[ni]);
        }
    }

    // epilogue: c0=(gid,2tg) c1=(gid,2tg+1) c2=(gid+8,2tg) c3=(gid+8,2tg+1)
    if (DOGELU) {
        #pragma unroll
        for (int mi = 0; mi < 4; mi++) {
            int rloc0 = m0 + wm * 64 + mi * 16 + gid;
            #pragma unroll
            for (int half = 0; half < 2; half++) {
                int rloc = rloc0 + half * 8;
                if (rloc >= cnt) continue;
                int grow = goff + rloc;
                __half* orow = (__half*)g_y1 + (size_t)grow * ND + n0;
                #pragma unroll
                for (int ni = 0; ni < 4; ni++) {
                    int c = wn * 32 + ni * 8 + tg * 2;
                    float v0 = acc[mi][ni][half * 2 + 0] + bias[n0 + c];
                    float v1 = acc[mi][ni][half * 2 + 1] + bias[n0 + c + 1];
                    *(__half2*)(orow + c) =
                        __floats2half2_rn(gelu_tanh(v0), gelu_tanh(v1));
                }
            }
        }
    } else {
        // Wv values for this thread's 8 columns
        float wv[8];
        #pragma unroll
        for (int ni = 0; ni < 4; ni++) {
            int c = wn * 32 + ni * 8 + tg * 2;
            wv[2 * ni]     = Wv[n0 + c];
            wv[2 * ni + 1] = Wv[n0 + c + 1];
        }
        #pragma unroll
        for (int mi = 0; mi < 4; mi++) {
            int rloc0 = m0 + wm * 64 + mi * 16 + gid;
            #pragma unroll
            for (int half = 0; half < 2; half++) {
                int rloc = rloc0 + half * 8;
                bool ok = (rloc < cnt);
                int gsafe = goff + (ok ? rloc : 0);
                int token = g_gtok[gsafe];
                float gate = g_ggate[gsafe];
                float vals[8];
                float s = 0.f;
                #pragma unroll
                for (int ni = 0; ni < 4; ni++) {
                    int c = wn * 32 + ni * 8 + tg * 2;
                    vals[2 * ni]     = gate * (acc[mi][ni][half * 2 + 0] + bias[n0 + c]);
                    vals[2 * ni + 1] = gate * (acc[mi][ni][half * 2 + 1] + bias[n0 + c + 1]);
                    s += vals[2 * ni] * wv[2 * ni] + vals[2 * ni + 1] * wv[2 * ni + 1];
                }
                // reduce over the 4 tg lanes (same row): lanes gid*4 + tg
                s += __shfl_xor_sync(0xffffffffu, s, 1);
                s += __shfl_xor_sync(0xffffffffu, s, 2);
                if (ok) {
                    float* orow = g_ffn + (size_t)token * ND + n0;
                    #pragma unroll
                    for (int ni = 0; ni < 4; ni++) {
                        int c = wn * 32 + ni * 8 + tg * 2;
                        orow[c]     = vals[2 * ni];
                        orow[c + 1] = vals[2 * ni + 1];
                    }
                    if (tg == 0)
                        g_vpart[token * 24 + blockIdx.y * 4 + wn] = s;
                }
            }
        }
    }
}

// sum the 24 deterministic partials -> v = clip(dot + bv); also reset g_cnt
__global__ void k_vsum(const float* __restrict__ bv) {
    int t = blockIdx.x * blockDim.x + threadIdx.x;
    if (t < Ee) g_cnt[t] = 0;
    float s = 0.f;
    #pragma unroll
    for (int j = 0; j < 24; j++) s += g_vpart[t * 24 + j];
    s += bv[0];
    g_v[t] = fminf(fmaxf(s, -V_MAX), V_MAX);
}

// ---------------- combined threshold (bitonic) + BK scan -------------------
struct CM2 { float r00,i00,r01,i01,r10,i10,r11,i11; };
__device__ __forceinline__ CM2 cm2_mul(const CM2& A, const CM2& B) {
    CM2 C;
    C.r00 = A.r00*B.r00 - A.i00*B.i00 + A.r01*B.r10 - A.i01*B.i10;
    C.i00 = A.r00*B.i00 + A.i00*B.r00 + A.r01*B.i10 + A.i01*B.r10;
    C.r01 = A.r00*B.r01 - A.i00*B.i01 + A.r01*B.r11 - A.i01*B.i11;
    C.i01 = A.r00*B.i01 + A.i00*B.r01 + A.r01*B.i11 + A.i01*B.r11;
    C.r10 = A.r10*B.r00 - A.i10*B.i00 + A.r11*B.r10 - A.i11*B.i10;
    C.i10 = A.r10*B.i00 + A.i10*B.r00 + A.r11*B.i10 + A.i11*B.r10;
    C.r11 = A.r10*B.r01 - A.i10*B.i01 + A.r11*B.r11 - A.i11*B.i11;
    C.i11 = A.r10*B.i01 + A.i10*B.r01 + A.r11*B.i11 + A.i11*B.r11;
    return C;
}
__device__ __forceinline__ void cm2_norm(CM2& A) {
    float mx = fmaxf(fmaxf(fabsf(A.r00)+fabsf(A.i00), fabsf(A.r01)+fabsf(A.i01)),
                     fmaxf(fabsf(A.r10)+fabsf(A.i10), fabsf(A.r11)+fabsf(A.i11)));
    float sc = 1.f / fmaxf(mx, 1e-30f);
    A.r00*=sc; A.i00*=sc; A.r01*=sc; A.i01*=sc;
    A.r10*=sc; A.i10*=sc; A.r11*=sc; A.i11*=sc;
}
__device__ __forceinline__ CM2 cm2_shfl_up(const CM2& A, int off) {
    CM2 B;
    B.r00 = __shfl_up_sync(0xffffffffu, A.r00, off);
    B.i00 = __shfl_up_sync(0xffffffffu, A.i00, off);
    B.r01 = __shfl_up_sync(0xffffffffu, A.r01, off);
    B.i01 = __shfl_up_sync(0xffffffffu, A.i01, off);
    B.r10 = __shfl_up_sync(0xffffffffu, A.r10, off);
    B.i10 = __shfl_up_sync(0xffffffffu, A.i10, off);
    B.r11 = __shfl_up_sync(0xffffffffu, A.r11, off);
    B.i11 = __shfl_up_sync(0xffffffffu, A.i11, off);
    return B;
}

__global__ void k_thrbk() {
    if (blockIdx.x < Bb) {
        // bitonic sort -> exact kth threshold
        __shared__ float s[Nn];
        int b = blockIdx.x, tid = threadIdx.x;
        for (int i = tid; i < Nn; i += 1024) s[i] = g_score[b * Nn + i];
        for (int k = 2; k <= Nn; k <<= 1) {
            for (int j = k >> 1; j > 0; j >>= 1) {
                __syncthreads();
                for (int i = tid; i < Nn; i += 1024) {
                    int ixj = i ^ j;
                    if (ixj > i) {
                        bool up = ((i & k) == 0);
                        float a = s[i], c = s[ixj];
                        if ((a > c) == up) { s[i] = c; s[ixj] = a; }
                    }
                }
            }
        }
        __syncthreads();
        if (tid == 0) g_thr[b] = s[Nn - KKEEP];
    } else if (threadIdx.x < 32) {
        int id = blockIdx.x - Bb;
        int b = id >> 1, dir = id & 1;
        int lane = threadIdx.x;
        const int CH = Nn / 32;   // 64
        const float* vv = g_v + b * Nn;

        CM2 P = {1,0, 0,0, 0,0, 1,0};
        for (int j = 0; j < CH; j++) {
            int idx = lane * CH + j;
            int pos = dir ? (Nn - 1 - idx) : idx;
            float dr = vv[pos];
            CM2 M = {dr, -1.f, -1.f, 0.f, 1.f, 0.f, 0.f, 0.f};
            P = cm2_mul(M, P);
            cm2_norm(P);
        }
        CM2 S = P;
        #pragma unroll
        for (int off = 1; off < 32; off <<= 1) {
            CM2 O = cm2_shfl_up(S, off);
            if (lane >= off) { S = cm2_mul(S, O); cm2_norm(S); }
        }
        CM2 E = cm2_shfl_up(S, 1);
        float ar, ai;
        if (lane == 0) { ar = 1e18f; ai = 0.f; }
        else {
            float nr = E.r00 * 1e18f + E.r01, ni = E.i00 * 1e18f + E.i01;
            float qr = E.r10 * 1e18f + E.r11, qi = E.i10 * 1e18f + E.i11;
            float den = qr * qr + qi * qi;
            if (den < 1e-36f) { ar = 1e18f; ai = 0.f; }
            else { ar = (nr * qr + ni * qi) / den; ai = (ni * qr - nr * qi) / den; }
        }
        float* outr = dir ? g_br : g_fr;
        float* outi = dir ? g_bi : g_fi;
        for (int j = 0; j < CH; j++) {
            int idx = lane * CH + j;
            int pos = dir ? (Nn - 1 - idx) : idx;
            float dr = vv[pos];
            float den = ar * ar + ai * ai;
            float inv = 1.f / den;
            float nr = dr - ar * inv;
            float ni = -1.f + ai * inv;
            ar = nr; ai = ni;
            outr[b * Nn + pos] = ar; outi[b * Nn + pos] = ai;
        }
    }
}

__global__ void k_out(const float* __restrict__ Wo, const float* __restrict__ bo,
                      const float* __restrict__ bk, float* __restrict__ out) {
    int t = blockIdx.x;
    int b = t >> 11;
    __shared__ float sfr, sfi, sbk;
    if (threadIdx.x == 0) {
        float v  = g_v[t];
        float cr = g_fr[t] + g_br[t] - v;
        float ci = g_fi[t] + g_bi[t] + 1.f;
        float den = cr * cr + ci * ci;
        float gr =  cr / den;
        float gi = -ci / den;
        float m = (g_score[t] >= g_thr[b]) ? 1.f : 0.f;
        sfr = fminf(fmaxf(gr * m, -FEAT_CLAMP), FEAT_CLAMP);
        sfi = fminf(fmaxf(gi * m, -FEAT_CLAMP), FEAT_CLAMP);
        sbk = bk[0];
    }
    __syncthreads();
    float fr = sfr, fi = sfi, s = sbk;
    for (int d = threadIdx.x; d < Dd; d += 192)
        out[(size_t)t * Dd + d] = g_ffn[t * Dd + d] + s * (fr * Wo[d] + fi * Wo[Dd + d] + bo[d]);
}

// ---------------- launch ---------------------------------------------------
extern "C" void kernel_launch(void* const* d_in, const int* in_sizes, int n_in,
                              void* d_out, int out_size) {
    const float* x   = (const float*)d_in[0];
    const float* Wg  = (const float*)d_in[1];
    const float* bg  = (const float*)d_in[2];
    const float* W1  = (const float*)d_in[3];
    const float* b1  = (const float*)d_in[4];
    const float* W2  = (const float*)d_in[5];
    const float* b2  = (const float*)d_in[6];
    const float* Wv  = (const float*)d_in[7];
    const float* bv  = (const float*)d_in[8];
    const float* Wm  = (const float*)d_in[9];
    const float* bm  = (const float*)d_in[10];
    const float* Wo  = (const float*)d_in[11];
    const float* bo  = (const float*)d_in[12];
    const float* bks = (const float*)d_in[13];
    float* out = (float*)d_out;

    static int attr_done = 0;
    if (!attr_done) {
        cudaFuncSetAttribute(k_gemm<Dd, Hh, true >,
                             cudaFuncAttributeMaxDynamicSharedMemorySize, GSMEM);
        cudaFuncSetAttribute(k_gemm<Hh, Dd, false>,
                             cudaFuncAttributeMaxDynamicSharedMemorySize, GSMEM);
        attr_done = 1;
    }

    k_gate<<<Tt, 256>>>(x, Wg, bg, Wm, bm);
    k_off<<<1, 1>>>();
    k_gather<<<Tt, 192>>>(x);
    k_tr<Dd, Hh, true ><<<dim3(Hh / 32, Dd / 64, Ee), dim3(32, 8)>>>(W1);
    k_tr<Hh, Dd, false><<<dim3(Dd / 32, Hh / 64, Ee), dim3(32, 8)>>>(W2);
    k_gemm<Dd, Hh, true ><<<dim3(Ee * 32, Hh / 128), 256, GSMEM>>>(b1, Wv);
    k_gemm<Hh, Dd, false><<<dim3(Ee * 32, Dd / 128), 256, GSMEM>>>(b2, Wv);
    k_vsum<<<Tt / 256, 256>>>(bv);
    k_thrbk<<<3 * Bb, 1024>>>();
    k_out<<<Tt, 192>>>(Wo, bo, bks, out);
}